// round 8
// baseline (speedup 1.0000x reference)
#include <cuda_runtime.h>

// Shapes (fixed):
//   p1: [6,256,256] f32   bank
//   p2: [131072,256] f32  table
//   p3: [6,1] i32         row ids into p2
//   p4: [1,256] i32       gather columns
//   p5: [6,1] i32         slot (c index) per batch
//   p6: [1,256] i32       scatter columns
//   p7: [6,256,256] f32   EMA state
//   p8: [12,6,256] f32    query features
// out1: [12,6,256] f32, out2: [6,256,256] f32 (concatenated in d_out)

#define B 6
#define S 256
#define D 256
#define A 12
#define ABD (A * B * D)  // 18432

// Role B (out1): one block per (b, 32-d chunk): 6*8 = 48 blocks.
#define NB_B (B * 8)
// Role A (out2): 16c x 64d tiles: 4 * 6 * 16 = 384 blocks.
#define CS_A 16
#define CLEN 16
#define DT 64
#define NB_A (4 * B * CS_A)

// Shared pool (floats):
//  role B: sB[256][34] (8704, later reused for 6144-float partial buffer)
//          | p8s[12][256] (3072) | gB[32]            -> 11808 floats (47.2 KB)
//  role A: sA[16][68] (1088) | gA[64] at +1088
#define POOL_FLOATS 11808

__global__ __launch_bounds__(256)
void fused_kernel(const float* __restrict__ p1,
                  const float* __restrict__ p2,
                  const int* __restrict__ p3,
                  const int* __restrict__ p4,
                  const int* __restrict__ p5,
                  const int* __restrict__ p6,
                  const float* __restrict__ p7,
                  const float* __restrict__ p8,
                  float* __restrict__ out1,
                  float* __restrict__ out2) {
    __shared__ __align__(16) float pool[POOL_FLOATS];
    const int id = blockIdx.x;
    const int t  = threadIdx.x;

    if (id < NB_B) {
        // ── Role B: out1 via smem-tile micro-GEMM, c parallelized ───────
        float* sB  = pool;                       // [256][34] add tile
        float* p8s = pool + 256 * 34;            // [12][256]
        float* g   = pool + 256 * 34 + A * 256;  // [32]

        const int b    = id >> 3;
        const int d0   = (id & 7) * 32;
        const int slot = p5[b];

        #pragma unroll
        for (int i = 0; i < A; i++)
            p8s[i * 256 + t] = p8[(i * B + b) * 256 + t];
        if (t < 8)
            ((float4*)g)[t] = ((const float4*)(p1 + (b * S + slot) * D + d0))[t];
        __syncthreads();
        {
            int col = p6[t];
            if (col >= d0 && col < d0 + 32)
                g[col - d0] = p2[(long long)p3[b] * D + p4[t]];
        }
        __syncthreads();

        // Build add tile: thread = (f4 d-lane fl, c-row cr), 8 c-iterations.
        const float* p1b = p1 + b * (S * D);
        const float* p7b = p7 + b * (S * D);
        const int fl = t & 7, cr = t >> 3;
        #pragma unroll
        for (int i = 0; i < 8; i++) {
            int c = cr + 32 * i;
            float4 v1 = ((const float4*)(p1b + c * D + d0))[fl];
            float4 v7 = ((const float4*)(p7b + c * D + d0))[fl];
            float4 bs = (c == slot) ? ((const float4*)g)[fl] : v1;
            float* row = sB + c * 34 + fl * 4;
            row[0] = fmaf(0.975f, v7.x, bs.x);
            row[1] = fmaf(0.975f, v7.y, bs.y);
            row[2] = fmaf(0.975f, v7.z, bs.z);
            row[3] = fmaf(0.975f, v7.w, bs.w);
        }
        __syncthreads();

        // GEMM phase: thread = (d-pair dp, c-strip st). 16 c per thread,
        // 12 float2 accumulators. Chain = 16 FMAs per scalar.
        const int dp = t & 15;
        const int st = t >> 4;
        float2 acc[A];
        #pragma unroll
        for (int a = 0; a < A; a++) acc[a] = make_float2(0.f, 0.f);
        #pragma unroll
        for (int j = 0; j < 16; j++) {
            int c = st * 16 + j;                 // ascending within strip
            float2 v = *(const float2*)(sB + c * 34 + dp * 2);
            #pragma unroll
            for (int a = 0; a < A; a++) {
                float w = p8s[a * 256 + c];
                acc[a].x = fmaf(w, v.x, acc[a].x);
                acc[a].y = fmaf(w, v.y, acc[a].y);
            }
        }
        __syncthreads();                         // everyone done reading sB

        // Store partials into reused sB region: red[(a*16+dp)*16 + st].
        float2* red = (float2*)pool;
        #pragma unroll
        for (int a = 0; a < A; a++)
            red[(a * 16 + dp) * 16 + st] = acc[a];
        __syncthreads();

        // Combine 16 strips in ascending order (= ascending c), write out1.
        if (t < A * 16) {
            const int a  = t >> 4;
            const int dpo = t & 15;
            const float2* r = red + t * 16;
            float2 sum = r[0];
            #pragma unroll
            for (int q = 1; q < 16; q++) {
                float2 p = r[q];
                sum.x += p.x; sum.y += p.y;
            }
            *(float2*)(out1 + (a * B + b) * 256 + d0 + dpo * 2) = sum;
        }
        return;
    }

    // ── Role A: out2 via transpose tile ─────────────────────────────────
    float* sA = pool;            // [16][68]
    float* gA = pool + 1088;     // [64], 16B-aligned

    const int k  = id - NB_B;
    const int d0 = (k & 3) * DT;
    const int b  = (k >> 2) % B;
    const int cs = k / (4 * B);
    const int c0 = cs * CLEN;
    const int slot = p5[b];

    if (t < DT / 4)
        ((float4*)gA)[t] = ((const float4*)(p1 + (b * S + slot) * D + d0))[t];
    __syncthreads();
    {
        int col = p6[t];
        if (col >= d0 && col < d0 + DT)
            gA[col - d0] = p2[(long long)p3[b] * D + p4[t]];
    }
    __syncthreads();

    const float* p1b = p1 + b * (S * D);
    const float* p7b = p7 + b * (S * D);
    float* out2b = out2 + b * (S * D);

    const int tx = t & 15;       // f4 d lane (64 d)
    const int ty = t >> 4;       // c lane (16 c)
    const int c  = c0 + ty;
    float4 v1 = ((const float4*)(p1b + c * D + d0))[tx];
    float4 v7 = ((const float4*)(p7b + c * D + d0))[tx];
    float4 bs = (c == slot) ? ((const float4*)gA)[tx] : v1;
    float4 val;
    val.x = fmaf(0.975f, v7.x, bs.x);
    val.y = fmaf(0.975f, v7.y, bs.y);
    val.z = fmaf(0.975f, v7.z, bs.z);
    val.w = fmaf(0.975f, v7.w, bs.w);
    ((float4*)(sA + ty * 68))[tx] = val;
    __syncthreads();

    {
        int cl  = t & 15;
        int dl0 = t >> 4;
        #pragma unroll
        for (int p = 0; p < 4; p++) {
            int dl = dl0 + p * 16;
            out2b[(d0 + dl) * D + c0 + cl] = sA[cl * 68 + dl];
        }
    }
}

extern "C" void kernel_launch(void* const* d_in, const int* in_sizes, int n_in,
                              void* d_out, int out_size) {
    const float* p1 = (const float*)d_in[0];
    const float* p2 = (const float*)d_in[1];
    const int*   p3 = (const int*)d_in[2];
    const int*   p4 = (const int*)d_in[3];
    const int*   p5 = (const int*)d_in[4];
    const int*   p6 = (const int*)d_in[5];
    const float* p7 = (const float*)d_in[6];
    const float* p8 = (const float*)d_in[7];

    float* out1 = (float*)d_out;                 // [12,6,256]
    float* out2 = out1 + ABD;                    // [6,256,256]

    fused_kernel<<<NB_A + NB_B, 256>>>(p1, p2, p3, p4, p5, p6, p7, p8, out1, out2);
}

// round 9
// speedup vs baseline: 1.2394x; 1.2394x over previous
#include <cuda_runtime.h>

// Shapes (fixed):
//   p1: [6,256,256] f32   bank
//   p2: [131072,256] f32  table
//   p3: [6,1] i32         row ids into p2
//   p4: [1,256] i32       gather columns
//   p5: [6,1] i32         slot (c index) per batch
//   p6: [1,256] i32       scatter columns
//   p7: [6,256,256] f32   EMA state
//   p8: [12,6,256] f32    query features
// out1: [12,6,256] f32, out2: [6,256,256] f32 (concatenated in d_out)

#define B 6
#define S 256
#define D 256
#define A 12
#define ABD (A * B * D)  // 18432

// Role B (out1): one block per (b, 32-d chunk): 6*8 = 48 blocks (ids 0..47).
#define NB_B (B * 8)
// Role A (out2): 64c x 64d tiles: 4 * 6 * 4 = 96 blocks.
#define NB_A (4 * B * 4)

// Shared pool (floats):
//  role B: sB[256][34] (8704) | p8s[12][256] (3072) | gB[32] -> 11808 (47.2 KB)
//  role A: sA[64][68] (4352)  | gA[64] at +4352
#define POOL_FLOATS 11808

__global__ __launch_bounds__(256)
void fused_kernel(const float* __restrict__ p1,
                  const float* __restrict__ p2,
                  const int* __restrict__ p3,
                  const int* __restrict__ p4,
                  const int* __restrict__ p5,
                  const int* __restrict__ p6,
                  const float* __restrict__ p7,
                  const float* __restrict__ p8,
                  float* __restrict__ out1,
                  float* __restrict__ out2) {
    __shared__ __align__(16) float pool[POOL_FLOATS];
    const int id = blockIdx.x;
    const int t  = threadIdx.x;

    if (id < NB_B) {
        // ── Role B: out1 via smem-tile micro-GEMM ───────────────────────
        float* sB  = pool;                       // [256][34] add tile
        float* p8s = pool + 256 * 34;            // [12][256]
        float* g   = pool + 256 * 34 + A * 256;  // [32]

        const int b    = id >> 3;
        const int d0   = (id & 7) * 32;
        const int slot = p5[b];

        #pragma unroll
        for (int i = 0; i < A; i++)
            p8s[i * 256 + t] = p8[(i * B + b) * 256 + t];
        if (t < 8)
            ((float4*)g)[t] = ((const float4*)(p1 + (b * S + slot) * D + d0))[t];
        __syncthreads();
        {
            int col = p6[t];
            if (col >= d0 && col < d0 + 32)
                g[col - d0] = p2[(long long)p3[b] * D + p4[t]];
        }
        __syncthreads();

        // Build add tile: thread = (f4 d-lane fl, c-row cr), 8 c-iterations.
        const float* p1b = p1 + b * (S * D);
        const float* p7b = p7 + b * (S * D);
        const int fl = t & 7, cr = t >> 3;
        #pragma unroll
        for (int i = 0; i < 8; i++) {
            int c = cr + 32 * i;
            float4 v1 = ((const float4*)(p1b + c * D + d0))[fl];
            float4 v7 = ((const float4*)(p7b + c * D + d0))[fl];
            float4 bs = (c == slot) ? ((const float4*)g)[fl] : v1;
            float* row = sB + c * 34 + fl * 4;
            row[0] = fmaf(0.975f, v7.x, bs.x);
            row[1] = fmaf(0.975f, v7.y, bs.y);
            row[2] = fmaf(0.975f, v7.z, bs.z);
            row[3] = fmaf(0.975f, v7.w, bs.w);
        }
        __syncthreads();

        // Micro-GEMM: 192 threads = (a, d-pair). 4 interleaved chains,
        // p8 fetched as float4 per 4 c. Fixed order -> deterministic.
        if (t < A * 16) {
            const int a  = t >> 4;
            const int dp = t & 15;
            const float* pr = p8s + a * 256;
            const float* sc = sB + dp * 2;
            float ax0 = 0.f, ax1 = 0.f, ax2 = 0.f, ax3 = 0.f;
            float ay0 = 0.f, ay1 = 0.f, ay2 = 0.f, ay3 = 0.f;
            #pragma unroll 8
            for (int c = 0; c < 256; c += 4) {
                float4 w  = *(const float4*)(pr + c);
                float2 v0 = *(const float2*)(sc + (c + 0) * 34);
                float2 v1 = *(const float2*)(sc + (c + 1) * 34);
                float2 v2 = *(const float2*)(sc + (c + 2) * 34);
                float2 v3 = *(const float2*)(sc + (c + 3) * 34);
                ax0 = fmaf(w.x, v0.x, ax0); ay0 = fmaf(w.x, v0.y, ay0);
                ax1 = fmaf(w.y, v1.x, ax1); ay1 = fmaf(w.y, v1.y, ay1);
                ax2 = fmaf(w.z, v2.x, ax2); ay2 = fmaf(w.z, v2.y, ay2);
                ax3 = fmaf(w.w, v3.x, ax3); ay3 = fmaf(w.w, v3.y, ay3);
            }
            float sx = (ax0 + ax1) + (ax2 + ax3);
            float sy = (ay0 + ay1) + (ay2 + ay3);
            int base = (a * B + b) * 256 + d0 + dp * 2;
            *(float2*)(out1 + base) = make_float2(sx, sy);
        }
        return;
    }

    // ── Role A: out2 via 64c x 64d transpose tile ───────────────────────
    float* sA = pool;            // [64][68]
    float* gA = pool + 64 * 68;  // [64], 16B-aligned (4352*4 % 16 == 0)

    const int k  = id - NB_B;
    const int d0 = (k & 3) * 64;
    const int b  = (k >> 2) % B;
    const int c0 = (k / (4 * B)) * 64;
    const int slot = p5[b];

    if (t < 16)
        ((float4*)gA)[t] = ((const float4*)(p1 + (b * S + slot) * D + d0))[t];
    __syncthreads();
    {
        int col = p6[t];
        if (col >= d0 && col < d0 + 64)
            gA[col - d0] = p2[(long long)p3[b] * D + p4[t]];
    }
    __syncthreads();

    const float* p1b = p1 + b * (S * D);
    const float* p7b = p7 + b * (S * D);
    float* out2b = out2 + b * (S * D);

    const int tx = t & 15;       // f4 d lane (64 d)
    const int ty = t >> 4;       // 16 c lanes, x4 iterations
    #pragma unroll
    for (int i = 0; i < 4; i++) {
        int cl = ty + 16 * i;
        int c  = c0 + cl;
        float4 v1 = ((const float4*)(p1b + c * D + d0))[tx];
        float4 v7 = ((const float4*)(p7b + c * D + d0))[tx];
        float4 bs = (c == slot) ? ((const float4*)gA)[tx] : v1;
        float4 val;
        val.x = fmaf(0.975f, v7.x, bs.x);
        val.y = fmaf(0.975f, v7.y, bs.y);
        val.z = fmaf(0.975f, v7.z, bs.z);
        val.w = fmaf(0.975f, v7.w, bs.w);
        ((float4*)(sA + cl * 68))[tx] = val;
    }
    __syncthreads();

    {
        int cl16 = t & 15;
        int dl0  = t >> 4;
        #pragma unroll
        for (int sub = 0; sub < 4; sub++) {
            #pragma unroll
            for (int p = 0; p < 4; p++) {
                int dl = dl0 + 16 * p;
                out2b[(d0 + dl) * D + c0 + sub * 16 + cl16] =
                    sA[(sub * 16 + cl16) * 68 + dl];
            }
        }
    }
}

extern "C" void kernel_launch(void* const* d_in, const int* in_sizes, int n_in,
                              void* d_out, int out_size) {
    const float* p1 = (const float*)d_in[0];
    const float* p2 = (const float*)d_in[1];
    const int*   p3 = (const int*)d_in[2];
    const int*   p4 = (const int*)d_in[3];
    const int*   p5 = (const int*)d_in[4];
    const int*   p6 = (const int*)d_in[5];
    const float* p7 = (const float*)d_in[6];
    const float* p8 = (const float*)d_in[7];

    float* out1 = (float*)d_out;                 // [12,6,256]
    float* out2 = out1 + ABD;                    // [6,256,256]

    fused_kernel<<<NB_A + NB_B, 256>>>(p1, p2, p3, p4, p5, p6, p7, p8, out1, out2);
}